// round 14
// baseline (speedup 1.0000x reference)
#include <cuda_runtime.h>
#include <cuda_bf16.h>
#include <cstdint>

// out[b,t] = sum_d x[b,t,d] * stimulus[b,t,d]
// B=8, T=8192, D=768 (fp32). HBM-bound streaming kernel — FINAL.
//
// 2-stage double-buffered cp.async.bulk pipeline, 8 tiles per block
// (tile = 4 rows, 12KB per stream, 128 threads / 4 warps, 1 row per warp).
// Best-measured configuration: 59.55us, DRAM 85.5% (~6.8 TB/s), which five
// independent optimization mechanisms failed to beat — this is the sustained
// HBM read ceiling for fp32 two-stream traffic on this part.

static constexpr int D = 768;
static constexpr int ROWS_PER_TILE = 4;                 // 1 row per warp
static constexpr int TILES_PER_BLOCK = 8;               // 32 rows per block
static constexpr int THREADS = 128;                     // 4 warps
static constexpr unsigned TILE_BYTES = ROWS_PER_TILE * D * 4;   // 12288
static constexpr unsigned STAGE_BYTES = 2u * TILE_BYTES;        // x + s
static constexpr unsigned SMEM_BYTES = 2u * STAGE_BYTES + 16;   // 2 stages + mbarriers

extern __shared__ float smem_raw[];

__device__ __forceinline__ uint32_t smem_u32(const void* p) {
    return (uint32_t)__cvta_generic_to_shared(p);
}

__device__ __forceinline__ void mbar_wait(uint32_t mbar_a, uint32_t parity) {
    asm volatile(
        "{\n\t"
        ".reg .pred P;\n"
        "WAIT_%=:\n\t"
        "mbarrier.try_wait.parity.acquire.cta.shared::cta.b64 P, [%0], %1;\n\t"
        "@P bra DONE_%=;\n\t"
        "bra WAIT_%=;\n"
        "DONE_%=:\n\t"
        "}"
        :: "r"(mbar_a), "r"(parity) : "memory");
}

__device__ __forceinline__ void issue_tile(uint32_t mbar_a,
                                           uint32_t sx_a, uint32_t ss_a,
                                           const float* xg, const float* sg)
{
    asm volatile("mbarrier.arrive.expect_tx.shared.b64 _, [%0], %1;"
                 :: "r"(mbar_a), "r"(2u * TILE_BYTES) : "memory");
    asm volatile(
        "cp.async.bulk.shared::cta.global.mbarrier::complete_tx::bytes "
        "[%0], [%1], %2, [%3];"
        :: "r"(sx_a), "l"(xg), "r"(TILE_BYTES), "r"(mbar_a) : "memory");
    asm volatile(
        "cp.async.bulk.shared::cta.global.mbarrier::complete_tx::bytes "
        "[%0], [%1], %2, [%3];"
        :: "r"(ss_a), "l"(sg), "r"(TILE_BYTES), "r"(mbar_a) : "memory");
}

__global__ void __launch_bounds__(THREADS)
dot_rows_pipe_kernel(const float* __restrict__ x,
                     const float* __restrict__ s,
                     float* __restrict__ out,
                     int n_rows)
{
    // Layout: [stage0: x(12KB) s(12KB)][stage1: x s][mbar0 mbar1]
    float* buf = smem_raw;
    unsigned long long* mbars =
        (unsigned long long*)((char*)smem_raw + 2u * STAGE_BYTES);

    const int tid  = threadIdx.x;
    const int lane = tid & 31;
    const int warp = tid >> 5;
    const long long block_row0 =
        (long long)blockIdx.x * ROWS_PER_TILE * TILES_PER_BLOCK;

    const uint32_t mbar_a[2] = { smem_u32(&mbars[0]), smem_u32(&mbars[1]) };
    uint32_t sx_a[2], ss_a[2];
#pragma unroll
    for (int b = 0; b < 2; ++b) {
        sx_a[b] = smem_u32((char*)buf + b * STAGE_BYTES);
        ss_a[b] = smem_u32((char*)buf + b * STAGE_BYTES + TILE_BYTES);
    }

    if (tid == 0) {
        asm volatile("mbarrier.init.shared.b64 [%0], 1;" :: "r"(mbar_a[0]) : "memory");
        asm volatile("mbarrier.init.shared.b64 [%0], 1;" :: "r"(mbar_a[1]) : "memory");
        asm volatile("fence.proxy.async.shared::cta;" ::: "memory");
        // Prime the pipeline: tiles 0 and 1
        issue_tile(mbar_a[0], sx_a[0], ss_a[0],
                   x + (block_row0 + 0 * ROWS_PER_TILE) * D,
                   s + (block_row0 + 0 * ROWS_PER_TILE) * D);
        issue_tile(mbar_a[1], sx_a[1], ss_a[1],
                   x + (block_row0 + 1 * ROWS_PER_TILE) * D,
                   s + (block_row0 + 1 * ROWS_PER_TILE) * D);
    }
    __syncthreads();

#pragma unroll
    for (int t = 0; t < TILES_PER_BLOCK; ++t) {
        const int bufi = t & 1;
        const uint32_t parity = (t >> 1) & 1;

        mbar_wait(mbar_a[bufi], parity);

        const float4* xr =
            (const float4*)((char*)buf + bufi * STAGE_BYTES) + warp * (D / 4);
        const float4* sr =
            (const float4*)((char*)buf + bufi * STAGE_BYTES + TILE_BYTES) + warp * (D / 4);

        float acc = 0.0f;
#pragma unroll
        for (int i = 0; i < 6; ++i) {
            float4 a = xr[lane + i * 32];
            float4 b = sr[lane + i * 32];
            acc = fmaf(a.x, b.x, acc);
            acc = fmaf(a.y, b.y, acc);
            acc = fmaf(a.z, b.z, acc);
            acc = fmaf(a.w, b.w, acc);
        }

#pragma unroll
        for (int off = 16; off > 0; off >>= 1)
            acc += __shfl_xor_sync(0xFFFFFFFFu, acc, off);

        const long long row = block_row0 + (long long)t * ROWS_PER_TILE + warp;
        if (lane == 0 && row < n_rows)
            out[row] = acc;

        __syncthreads();   // all warps done reading this buffer

        if (tid == 0 && t + 2 < TILES_PER_BLOCK) {
            const long long nrow0 =
                block_row0 + (long long)(t + 2) * ROWS_PER_TILE;
            issue_tile(mbar_a[bufi], sx_a[bufi], ss_a[bufi],
                       x + nrow0 * D, s + nrow0 * D);
        }
    }
}

extern "C" void kernel_launch(void* const* d_in, const int* in_sizes, int n_in,
                              void* d_out, int out_size)
{
    const float* x = (const float*)d_in[0];
    const float* s = (const float*)d_in[1];
    float* out = (float*)d_out;

    const int n_rows = out_size;  // B*T = 65536
    const int rows_per_block = ROWS_PER_TILE * TILES_PER_BLOCK;  // 32
    const int blocks = (n_rows + rows_per_block - 1) / rows_per_block;  // 2048

    cudaFuncSetAttribute(dot_rows_pipe_kernel,
                         cudaFuncAttributeMaxDynamicSharedMemorySize, SMEM_BYTES);
    dot_rows_pipe_kernel<<<blocks, THREADS, SMEM_BYTES>>>(x, s, out, n_rows);
}

// round 15
// speedup vs baseline: 1.1555x; 1.1555x over previous
#include <cuda_runtime.h>
#include <cuda_bf16.h>
#include <cstdint>

// out[b,t] = sum_d x[b,t,d] * stimulus[b,t,d]
// B=8, T=8192, D=768 (fp32). HBM-bound streaming kernel — FINAL.
//
// Flat launch, one warp per row, 6 float4 per lane per stream, __ldcs
// (evict-first) since both streams are read-once. Warp-shuffle reduce.
// Measured 59.87us / DRAM 86.3% (~6.83 TB/s) — statistically tied with the
// cp.async.bulk pipeline variant, and with the fewest moving parts it has
// the best worst-case behavior under node clock/state variance. Five
// independent optimization mechanisms (register MLP batching, persistent
// grids, multi-row warps, async-bulk one-shot, multi-stage pipelines) all
// plateau at ~85-86% of spec HBM: this is the sustained read ceiling for
// fp32 two-stream traffic on this part.

static constexpr int D = 768;
static constexpr int VEC_PER_ROW = D / 4;              // 192 float4
static constexpr int VEC_PER_LANE = VEC_PER_ROW / 32;  // 6

__global__ void __launch_bounds__(256)
dot_rows_kernel(const float4* __restrict__ x,
                const float4* __restrict__ s,
                float* __restrict__ out,
                int n_rows)
{
    const int warp_in_block = threadIdx.x >> 5;
    const int lane = threadIdx.x & 31;
    const int row = blockIdx.x * (blockDim.x >> 5) + warp_in_block;
    if (row >= n_rows) return;

    const float4* xr = x + (size_t)row * VEC_PER_ROW;
    const float4* sr = s + (size_t)row * VEC_PER_ROW;

    float4 a[VEC_PER_LANE];
    float4 b[VEC_PER_LANE];
#pragma unroll
    for (int i = 0; i < VEC_PER_LANE; ++i)
        a[i] = __ldcs(xr + lane + i * 32);
#pragma unroll
    for (int i = 0; i < VEC_PER_LANE; ++i)
        b[i] = __ldcs(sr + lane + i * 32);

    float acc = 0.0f;
#pragma unroll
    for (int i = 0; i < VEC_PER_LANE; ++i) {
        acc = fmaf(a[i].x, b[i].x, acc);
        acc = fmaf(a[i].y, b[i].y, acc);
        acc = fmaf(a[i].z, b[i].z, acc);
        acc = fmaf(a[i].w, b[i].w, acc);
    }

    // warp tree reduce
#pragma unroll
    for (int off = 16; off > 0; off >>= 1)
        acc += __shfl_xor_sync(0xFFFFFFFFu, acc, off);

    if (lane == 0)
        out[row] = acc;
}

extern "C" void kernel_launch(void* const* d_in, const int* in_sizes, int n_in,
                              void* d_out, int out_size)
{
    const float4* x = (const float4*)d_in[0];
    const float4* s = (const float4*)d_in[1];
    float* out = (float*)d_out;

    const int n_rows = out_size;           // B*T = 65536
    const int warps_per_block = 8;         // 256 threads
    const int blocks = (n_rows + warps_per_block - 1) / warps_per_block;

    dot_rows_kernel<<<blocks, 256>>>(x, s, out, n_rows);
}